// round 15
// baseline (speedup 1.0000x reference)
#include <cuda_runtime.h>
#include <cuda_bf16.h>

#define THREADS      256
#define WARPS        (THREADS / 32)
#define ITERS        2
#define F4_PER_WI    64                      // float4 per warp-iteration (256 floats = 4 blocks)
#define F4_PER_CI    (WARPS * F4_PER_WI)     // 512 float4 per CTA-iteration
#define F4_PER_CTA   (F4_PER_CI * ITERS)     // 1024 float4 = 4096 floats per CTA

// Cell map: j = rne(v*16) + 16 in [0,32]  (cell width 1/16 = 0.0625 < min
// NF4-midpoint gap 0.0853 -> each cell holds at most one midpoint).
//   thr_rep[j*32+lane]      = midpoint inside cell j (2.0f sentinel if none)
//   lvl_rep[(2j+g)*32+lane] = NF4[ b(j) + g ],  b(j) = #midpoints in cells < j
// idx = b(j) + (v > thr)  ==  searchsorted(mids, v, side=left)  exactly:
// the rne cell map is monotone, so cross-cell ordering is preserved; the
// in-cell case is a direct fp32 compare against the exact midpoint.
// Tables are lane-replicated -> structurally conflict-free LDS (1 wf each).

// Per-cell scalars, computed directly (redundantly per thread; hidden under
// the global-load latency window).
__device__ __forceinline__ void cell_scalars(int j, float& thr, float& lo, float& hi)
{
    const float nf4[16] = {
        -1.0f, -0.6961928f, -0.52507305f, -0.39491749f, -0.28444138f,
        -0.18477343f, -0.09105004f, 0.0f, 0.0795803f, 0.1609302f,
        0.2461123f, 0.33791524f, 0.44070983f, 0.562617f, 0.72295684f, 1.0f};
    int b = 0; thr = 2.0f; bool found = false;
    #pragma unroll
    for (int k = 0; k < 15; k++) {
        float mid = 0.5f * (nf4[k] + nf4[k + 1]);
        int jm = (int)(__float_as_uint(fmaf(mid, 16.0f, 8388624.0f)) & 0x3Fu);
        if (jm < j) b++;
        else if (jm == j) { thr = mid; found = true; }
    }
    lo = nf4[b];
    hi = nf4[found ? b + 1 : b];
}

template<bool GUARD>
__global__ __launch_bounds__(THREADS) void nf4_quant_kernel(
    const float4* __restrict__ w4,
    const float* __restrict__ log_scale,
    float4* __restrict__ o4,
    int n4, int f4_offset)
{
    __shared__ float thr_rep[33 * 32];
    __shared__ float lvl_rep[66 * 32];

    const unsigned lane = threadIdx.x & 31u;
    const int      warp = threadIdx.x >> 5;

    // 8 lanes per 64-float block: lane owns float4 [blk*16 + p] and [blk*16 + 8 + p]
    const int toff  = ((int)(lane >> 3)) * 16 + (int)(lane & 7u);
    const int base0 = f4_offset + blockIdx.x * F4_PER_CTA + warp * F4_PER_WI + toff;

    // ── Loads FIRST: start the DRAM stream before any prologue work. The
    // table build + expf below then hide entirely under load latency.
    float4 a0 = make_float4(0.f,0.f,0.f,0.f), c0 = a0;
    float4 a1 = a0, c1 = a0;
    if (!GUARD || base0 < n4)                  a0 = __ldcs(&w4[base0]);
    if (!GUARD || base0 + 8 < n4)              c0 = __ldcs(&w4[base0 + 8]);
    if (!GUARD || base0 + F4_PER_CI < n4)      a1 = __ldcs(&w4[base0 + F4_PER_CI]);
    if (!GUARD || base0 + F4_PER_CI + 8 < n4)  c1 = __ldcs(&w4[base0 + F4_PER_CI + 8]);

    const float e = expf(__ldg(log_scale));   // MUFU chain hides under LDG window

    // Single-phase table build: each thread computes and splat-stores its own
    // vector rows directly (no staging arrays, ONE barrier).
    // thr: 33 rows x 8 float4 = 264 vec;  lvl: 66 rows x 8 float4 = 528 vec.
    {
        float4* thr4 = (float4*)thr_rep;
        float4* lvl4 = (float4*)lvl_rep;
        float thr, lo, hi;
        #pragma unroll 2
        for (int t = threadIdx.x; t < 264 + 528; t += THREADS) {
            if (t < 264) {
                cell_scalars(t >> 3, thr, lo, hi);
                thr4[t] = make_float4(thr, thr, thr, thr);
            } else {
                int tt = t - 264;
                int row = tt >> 3;
                cell_scalars(row >> 1, thr, lo, hi);
                float s = (row & 1) ? hi : lo;
                lvl4[tt] = make_float4(s, s, s, s);
            }
        }
    }
    __syncthreads();

    const float* __restrict__ thr_lane = thr_rep + lane;
    const float* __restrict__ lvl_lane = lvl_rep + lane;

    #pragma unroll
    for (int i = 0; i < ITERS; i++) {
        const int idx = base0 + i * F4_PER_CI;

        // block absmax: 8 floats local, then 8-lane butterfly (stays in blk group)
        float m = fmaxf(fmaxf(fmaxf(fabsf(a0.x), fabsf(a0.y)), fmaxf(fabsf(a0.z), fabsf(a0.w))),
                        fmaxf(fmaxf(fabsf(c0.x), fabsf(c0.y)), fmaxf(fabsf(c0.z), fabsf(c0.w))));
        m = fmaxf(m, __shfl_xor_sync(0xffffffffu, m, 1));
        m = fmaxf(m, __shfl_xor_sync(0xffffffffu, m, 2));
        m = fmaxf(m, __shfl_xor_sync(0xffffffffu, m, 4));

        const float scale = fmaxf(m * e, 1e-6f);
        const float inv   = 1.0f / scale;

        float4 ra, rc;
        {
            float v, thr; unsigned j, g;
            #define Q(dst, src)                                                      \
                v   = fminf(fmaxf((src) * inv, -1.0f), 1.0f);                        \
                j   = __float_as_uint(fmaf(v, 16.0f, 8388624.0f)) & 0x3Fu;           \
                thr = thr_lane[j * 32u];                                             \
                g   = (v > thr) ? 1u : 0u;                                           \
                dst = lvl_lane[(2u * j + g) * 32u] * scale;
            Q(ra.x, a0.x) Q(ra.y, a0.y) Q(ra.z, a0.z) Q(ra.w, a0.w)
            Q(rc.x, c0.x) Q(rc.y, c0.y) Q(rc.z, c0.z) Q(rc.w, c0.w)
            #undef Q
        }

        if (!GUARD || idx < n4)     __stcs(&o4[idx], ra);
        if (!GUARD || idx + 8 < n4) __stcs(&o4[idx + 8], rc);

        a0 = a1; c0 = c1;
    }
}

extern "C" void kernel_launch(void* const* d_in, const int* in_sizes, int n_in,
                              void* d_out, int out_size)
{
    const float4* w4 = (const float4*)d_in[0];
    const float*  ls = (const float*)d_in[1];
    float4*       o4 = (float4*)d_out;

    const int n  = in_sizes[0];          // divisible by 64 (BLOCK)
    const int n4 = n >> 2;               // float4 count

    const int full = n4 / F4_PER_CTA;    // CTAs with no bounds checks needed
    const int rem  = n4 - full * F4_PER_CTA;

    if (full > 0)
        nf4_quant_kernel<false><<<full, THREADS>>>(w4, ls, o4, n4, 0);
    if (rem > 0) {
        const int gridr = (rem + F4_PER_CTA - 1) / F4_PER_CTA;
        nf4_quant_kernel<true><<<gridr, THREADS>>>(w4, ls, o4, n4, full * F4_PER_CTA);
    }
}

// round 16
// speedup vs baseline: 1.3949x; 1.3949x over previous
#include <cuda_runtime.h>
#include <cuda_bf16.h>

#define THREADS      256
#define WARPS        (THREADS / 32)
#define ITERS        2
#define F4_PER_WI    64                      // float4 per warp-iteration (256 floats = 4 blocks)
#define F4_PER_CI    (WARPS * F4_PER_WI)     // 512 float4 per CTA-iteration
#define F4_PER_CTA   (F4_PER_CI * ITERS)     // 1024 float4 = 4096 floats per CTA

// Cell map: j = rne(v*16) + 16 in [0,32]  (cell width 1/16 = 0.0625 < min
// NF4-midpoint gap 0.0853 -> each cell holds at most one midpoint).
//   thr_rep[j*32+lane]      = midpoint inside cell j (2.0f sentinel if none)
//   lvl_rep[(2j+g)*32+lane] = NF4[ b(j) + g ],  b(j) = #midpoints in cells < j
// idx = b(j) + (v > thr)  ==  searchsorted(mids, v, side=left)  exactly:
// the rne cell map is monotone, so cross-cell ordering is preserved; the
// in-cell case is a direct fp32 compare against the exact midpoint.
// Tables are lane-replicated -> structurally conflict-free LDS (1 wf each).

template<bool GUARD>
__global__ __launch_bounds__(THREADS) void nf4_quant_kernel(
    const float4* __restrict__ w4,
    const float* __restrict__ log_scale,
    float4* __restrict__ o4,
    int n4, int f4_offset)
{
    __shared__ float thr_rep[33 * 32];
    __shared__ float lvl_rep[66 * 32];
    __shared__ float thr_s[33], lo_s[33], hi_s[33];

    const unsigned lane = threadIdx.x & 31u;
    const int      warp = threadIdx.x >> 5;

    // 8 lanes per 64-float block: lane owns float4 [blk*16 + p] and [blk*16 + 8 + p]
    const int toff  = ((int)(lane >> 3)) * 16 + (int)(lane & 7u);
    const int base0 = f4_offset + blockIdx.x * F4_PER_CTA + warp * F4_PER_WI + toff;

    // ── Loads FIRST: start the DRAM stream before any prologue work. The
    // table build below (~400 cyc) then hides entirely under load latency.
    float4 a0 = make_float4(0.f,0.f,0.f,0.f), c0 = a0;
    float4 a1 = a0, c1 = a0;
    if (!GUARD || base0 < n4)                  a0 = __ldcs(&w4[base0]);
    if (!GUARD || base0 + 8 < n4)              c0 = __ldcs(&w4[base0 + 8]);
    if (!GUARD || base0 + F4_PER_CI < n4)      a1 = __ldcs(&w4[base0 + F4_PER_CI]);
    if (!GUARD || base0 + F4_PER_CI + 8 < n4)  c1 = __ldcs(&w4[base0 + F4_PER_CI + 8]);

    // Phase 1: 33 threads compute per-cell scalars (everyone else skips).
    // Confined to few threads so the nf4[] table stays register-resident.
    if (threadIdx.x < 33) {
        const float nf4[16] = {
            -1.0f, -0.6961928f, -0.52507305f, -0.39491749f, -0.28444138f,
            -0.18477343f, -0.09105004f, 0.0f, 0.0795803f, 0.1609302f,
            0.2461123f, 0.33791524f, 0.44070983f, 0.562617f, 0.72295684f, 1.0f};
        const int j = threadIdx.x;
        int b = 0; float thr = 2.0f; bool found = false;
        #pragma unroll
        for (int k = 0; k < 15; k++) {
            float mid = 0.5f * (nf4[k] + nf4[k + 1]);
            int jm = (int)(__float_as_uint(fmaf(mid, 16.0f, 8388624.0f)) & 0x3Fu);
            if (jm < j) b++;
            else if (jm == j) { thr = mid; found = true; }
        }
        thr_s[j] = thr;
        lo_s[j]  = nf4[b];
        hi_s[j]  = nf4[found ? b + 1 : b];
    }
    __syncthreads();

    // Phase 2: replicate via splat STS.128 (rows are constant -> 4 lanes/store).
    {
        float4* thr4 = (float4*)thr_rep;
        float4* lvl4 = (float4*)lvl_rep;
        for (int t = threadIdx.x; t < 33 * 8; t += THREADS) {
            float s = thr_s[t >> 3];
            thr4[t] = make_float4(s, s, s, s);
        }
        for (int t = threadIdx.x; t < 66 * 8; t += THREADS) {
            int row = t >> 3, j = row >> 1;
            float s = (row & 1) ? hi_s[j] : lo_s[j];
            lvl4[t] = make_float4(s, s, s, s);
        }
    }
    __syncthreads();

    const float e = expf(__ldg(log_scale));
    const float* __restrict__ thr_lane = thr_rep + lane;
    const float* __restrict__ lvl_lane = lvl_rep + lane;

    #pragma unroll
    for (int i = 0; i < ITERS; i++) {
        const int idx = base0 + i * F4_PER_CI;

        // block absmax: 8 floats local, then 8-lane butterfly (stays in blk group)
        float m = fmaxf(fmaxf(fmaxf(fabsf(a0.x), fabsf(a0.y)), fmaxf(fabsf(a0.z), fabsf(a0.w))),
                        fmaxf(fmaxf(fabsf(c0.x), fabsf(c0.y)), fmaxf(fabsf(c0.z), fabsf(c0.w))));
        m = fmaxf(m, __shfl_xor_sync(0xffffffffu, m, 1));
        m = fmaxf(m, __shfl_xor_sync(0xffffffffu, m, 2));
        m = fmaxf(m, __shfl_xor_sync(0xffffffffu, m, 4));

        const float scale = fmaxf(m * e, 1e-6f);
        const float inv   = 1.0f / scale;

        float4 ra, rc;
        {
            float v, thr; unsigned j, g;
            #define Q(dst, src)                                                      \
                v   = fminf(fmaxf((src) * inv, -1.0f), 1.0f);                        \
                j   = __float_as_uint(fmaf(v, 16.0f, 8388624.0f)) & 0x3Fu;           \
                thr = thr_lane[j * 32u];                                             \
                g   = (v > thr) ? 1u : 0u;                                           \
                dst = lvl_lane[(2u * j + g) * 32u] * scale;
            Q(ra.x, a0.x) Q(ra.y, a0.y) Q(ra.z, a0.z) Q(ra.w, a0.w)
            Q(rc.x, c0.x) Q(rc.y, c0.y) Q(rc.z, c0.z) Q(rc.w, c0.w)
            #undef Q
        }

        if (!GUARD || idx < n4)     __stcs(&o4[idx], ra);
        if (!GUARD || idx + 8 < n4) __stcs(&o4[idx + 8], rc);

        a0 = a1; c0 = c1;
    }
}

extern "C" void kernel_launch(void* const* d_in, const int* in_sizes, int n_in,
                              void* d_out, int out_size)
{
    const float4* w4 = (const float4*)d_in[0];
    const float*  ls = (const float*)d_in[1];
    float4*       o4 = (float4*)d_out;

    const int n  = in_sizes[0];          // divisible by 64 (BLOCK)
    const int n4 = n >> 2;               // float4 count

    const int full = n4 / F4_PER_CTA;    // CTAs with no bounds checks needed
    const int rem  = n4 - full * F4_PER_CTA;

    if (full > 0)
        nf4_quant_kernel<false><<<full, THREADS>>>(w4, ls, o4, n4, 0);
    if (rem > 0) {
        const int gridr = (rem + F4_PER_CTA - 1) / F4_PER_CTA;
        nf4_quant_kernel<true><<<gridr, THREADS>>>(w4, ls, o4, n4, full * F4_PER_CTA);
    }
}

// round 17
// speedup vs baseline: 1.4040x; 1.0065x over previous
#include <cuda_runtime.h>
#include <cuda_bf16.h>

#define THREADS      256
#define WARPS        (THREADS / 32)
#define ITERS        2
#define F4_PER_WI    64                      // float4 per warp-iteration (256 floats = 4 blocks)
#define F4_PER_CI    (WARPS * F4_PER_WI)     // 512 float4 per CTA-iteration
#define F4_PER_CTA   (F4_PER_CI * ITERS)     // 1024 float4 = 4096 floats per CTA

// Cell map: j = rne(v*16) + 16 in [0,32]  (cell width 1/16 = 0.0625 < min
// NF4-midpoint gap 0.0853 -> each cell holds at most one midpoint).
//   thr_rep[j*32+lane]      = midpoint inside cell j (2.0f sentinel if none)
//   lvl_rep[(2j+g)*32+lane] = NF4[ b(j) + g ],  b(j) = #midpoints in cells < j
// idx = b(j) + (v > thr)  ==  searchsorted(mids, v, side=left)  exactly:
// the rne cell map is monotone, so cross-cell ordering is preserved; the
// in-cell case is a direct fp32 compare against the exact midpoint.
// Tables are lane-replicated -> structurally conflict-free LDS (1 wf each).

template<bool GUARD>
__global__ __launch_bounds__(THREADS) void nf4_quant_kernel(
    const float4* __restrict__ w4,
    const float* __restrict__ log_scale,
    float4* __restrict__ o4,
    int n4, int f4_offset)
{
    __shared__ float thr_rep[33 * 32];
    __shared__ float lvl_rep[66 * 32];
    __shared__ float thr_s[33], lo_s[33], hi_s[33];

    const unsigned lane = threadIdx.x & 31u;
    const int      warp = threadIdx.x >> 5;

    // 8 lanes per 64-float block: lane owns float4 [blk*16 + p] and [blk*16 + 8 + p]
    const int toff  = ((int)(lane >> 3)) * 16 + (int)(lane & 7u);
    const int base0 = f4_offset + blockIdx.x * F4_PER_CTA + warp * F4_PER_WI + toff;

    // ── Loads FIRST: start the DRAM stream before any prologue work. The
    // table build + expf below then hide entirely under load latency.
    float4 a0 = make_float4(0.f,0.f,0.f,0.f), c0 = a0;
    float4 a1 = a0, c1 = a0;
    if (!GUARD || base0 < n4)                  a0 = __ldcs(&w4[base0]);
    if (!GUARD || base0 + 8 < n4)              c0 = __ldcs(&w4[base0 + 8]);
    if (!GUARD || base0 + F4_PER_CI < n4)      a1 = __ldcs(&w4[base0 + F4_PER_CI]);
    if (!GUARD || base0 + F4_PER_CI + 8 < n4)  c1 = __ldcs(&w4[base0 + F4_PER_CI + 8]);

    // Scalar load + MUFU chain also hidden under the LDG window.
    const float e = expf(__ldg(log_scale));

    // Phase 1: 33 threads compute per-cell scalars (everyone else skips).
    // Confined to few threads so the nf4[] table stays register-resident.
    if (threadIdx.x < 33) {
        const float nf4[16] = {
            -1.0f, -0.6961928f, -0.52507305f, -0.39491749f, -0.28444138f,
            -0.18477343f, -0.09105004f, 0.0f, 0.0795803f, 0.1609302f,
            0.2461123f, 0.33791524f, 0.44070983f, 0.562617f, 0.72295684f, 1.0f};
        const int j = threadIdx.x;
        int b = 0; float thr = 2.0f; bool found = false;
        #pragma unroll
        for (int k = 0; k < 15; k++) {
            float mid = 0.5f * (nf4[k] + nf4[k + 1]);
            int jm = (int)(__float_as_uint(fmaf(mid, 16.0f, 8388624.0f)) & 0x3Fu);
            if (jm < j) b++;
            else if (jm == j) { thr = mid; found = true; }
        }
        thr_s[j] = thr;
        lo_s[j]  = nf4[b];
        hi_s[j]  = nf4[found ? b + 1 : b];
    }
    __syncthreads();

    // Phase 2: replicate via splat STS.128 (rows are constant -> 4 lanes/store).
    {
        float4* thr4 = (float4*)thr_rep;
        float4* lvl4 = (float4*)lvl_rep;
        for (int t = threadIdx.x; t < 33 * 8; t += THREADS) {
            float s = thr_s[t >> 3];
            thr4[t] = make_float4(s, s, s, s);
        }
        for (int t = threadIdx.x; t < 66 * 8; t += THREADS) {
            int row = t >> 3, j = row >> 1;
            float s = (row & 1) ? hi_s[j] : lo_s[j];
            lvl4[t] = make_float4(s, s, s, s);
        }
    }
    __syncthreads();

    const float* __restrict__ thr_lane = thr_rep + lane;
    const float* __restrict__ lvl_lane = lvl_rep + lane;

    #pragma unroll
    for (int i = 0; i < ITERS; i++) {
        const int idx = base0 + i * F4_PER_CI;

        // block absmax: 8 floats local, then 8-lane butterfly (stays in blk group)
        float m = fmaxf(fmaxf(fmaxf(fabsf(a0.x), fabsf(a0.y)), fmaxf(fabsf(a0.z), fabsf(a0.w))),
                        fmaxf(fmaxf(fabsf(c0.x), fabsf(c0.y)), fmaxf(fabsf(c0.z), fabsf(c0.w))));
        m = fmaxf(m, __shfl_xor_sync(0xffffffffu, m, 1));
        m = fmaxf(m, __shfl_xor_sync(0xffffffffu, m, 2));
        m = fmaxf(m, __shfl_xor_sync(0xffffffffu, m, 4));

        const float scale = fmaxf(m * e, 1e-6f);
        const float inv   = 1.0f / scale;

        float4 ra, rc;
        {
            float v, thr; unsigned j, g;
            #define Q(dst, src)                                                      \
                v   = fminf(fmaxf((src) * inv, -1.0f), 1.0f);                        \
                j   = __float_as_uint(fmaf(v, 16.0f, 8388624.0f)) & 0x3Fu;           \
                thr = thr_lane[j * 32u];                                             \
                g   = (v > thr) ? 1u : 0u;                                           \
                dst = lvl_lane[(2u * j + g) * 32u] * scale;
            Q(ra.x, a0.x) Q(ra.y, a0.y) Q(ra.z, a0.z) Q(ra.w, a0.w)
            Q(rc.x, c0.x) Q(rc.y, c0.y) Q(rc.z, c0.z) Q(rc.w, c0.w)
            #undef Q
        }

        if (!GUARD || idx < n4)     __stcs(&o4[idx], ra);
        if (!GUARD || idx + 8 < n4) __stcs(&o4[idx + 8], rc);

        a0 = a1; c0 = c1;
    }
}

extern "C" void kernel_launch(void* const* d_in, const int* in_sizes, int n_in,
                              void* d_out, int out_size)
{
    const float4* w4 = (const float4*)d_in[0];
    const float*  ls = (const float*)d_in[1];
    float4*       o4 = (float4*)d_out;

    const int n  = in_sizes[0];          // divisible by 64 (BLOCK)
    const int n4 = n >> 2;               // float4 count

    const int full = n4 / F4_PER_CTA;    // CTAs with no bounds checks needed
    const int rem  = n4 - full * F4_PER_CTA;

    if (full > 0)
        nf4_quant_kernel<false><<<full, THREADS>>>(w4, ls, o4, n4, 0);
    if (rem > 0) {
        const int gridr = (rem + F4_PER_CTA - 1) / F4_PER_CTA;
        nf4_quant_kernel<true><<<gridr, THREADS>>>(w4, ls, o4, n4, full * F4_PER_CTA);
    }
}